// round 7
// baseline (speedup 1.0000x reference)
#include <cuda_runtime.h>

// Problem constants (fixed by reference_code)
#define LSEQ 8192
#define BATCH 32
#define CIN 7
#define KER 73            // 512 // 7
#define DM 512
#define RT 16             // output rows per tile
#define SL 128            // rows per strip work-item
#define TILES (SL / RT)   // 8
#define WROWS (SL + RT + 1)   // 145 window rows: strip + 16 back + 1 fwd
#define WELEMS (WROWS * CIN)  // 1015
#define SPB (LSEQ / SL)       // 64 strips per batch row
#define NSTRIPS (SPB * BATCH) // 2048
#define NBLOCKS 296           // 148 SMs x 2 resident: exactly one wave

// out[b, n, c*73+k] = conv_b[k] + sum_{j=0..17} W2[k][j] * x[b, n+1-j, c]
//   W2[k][j] = conv_w[k][ (j/3)*3 + (2 - j%3) ]
// Conv position p = n-1+t contributes only if (after circular wrap) p >= 15.
// Interior rows 16..L-2 are unconditionally valid (fast path).
//
// Persistent grid: weights loaded once per block; blocks grid-stride over
// 2048 strips (6.9 per block -> ~1% imbalance, no wave-tail quantization).

__global__ __launch_bounds__(512, 2)
void tokemb_kernel(const float* __restrict__ x,
                   const float* __restrict__ conv_w,
                   const float* __restrict__ conv_b,
                   const float* __restrict__ left_w,
                   const float* __restrict__ left_b,
                   float* __restrict__ out)
{
    const int d = threadIdx.x;           // output channel 0..511

    // Per-thread channel / weights / bias: loaded ONCE per persistent block.
    const bool main_ch = (d < CIN * KER);            // d < 511
    const int  c    = main_ch ? (d / KER) : (CIN - 1);
    const float* wsrc = main_ch ? (conv_w + (d % KER) * 18) : left_w;
    const float bias  = main_ch ? conv_b[d % KER] : left_b[0];

    float w[18];
    #pragma unroll
    for (int j = 0; j < 18; ++j)
        w[j] = wsrc[(j / 3) * 3 + 2 - (j % 3)];

    // Double-buffered strip window: one __syncthreads per strip.
    // stage(s+1) writes the buffer last read at strip s-1; the strip-s
    // barrier already ordered those reads before this write.
    __shared__ float xs[2][WELEMS];

    const bool second = (d + 512 < WELEMS);   // 503 threads load 2 elements

    int pb = 0;
    #pragma unroll 1
    for (int sid = blockIdx.x; sid < NSTRIPS; sid += NBLOCKS, pb ^= 1) {
        const int b  = sid >> 6;             // sid / SPB
        const int s0 = (sid & (SPB - 1)) * SL;
        const float* xb = x + (size_t)b * LSEQ * CIN;

        // Stage x[b, s0-16 .. s0+SL, :] (1015 floats), index-clamped.
        // Clamped junk rows are only consumed by slow-path strips (which
        // bypass smem entirely).
        {
            const int gbase = (s0 - RT) * CIN;   // negative at s0 = 0
            int g0 = gbase + d;
            g0 = min(max(g0, 0), LSEQ * CIN - 1);
            xs[pb][d] = xb[g0];
            if (second) {
                int g1 = gbase + d + 512;
                g1 = min(max(g1, 0), LSEQ * CIN - 1);
                xs[pb][d + 512] = xb[g1];
            }
        }
        __syncthreads();

        float* outp = out + ((size_t)(b * LSEQ + s0)) * DM + d;

        if ((s0 >= 16) && (s0 + SL <= LSEQ - 1)) {
            // Fast path: value-outer register-resident FIR, RT rows per tile.
            #pragma unroll 1
            for (int t = 0; t < TILES; ++t) {
                const float* xcol = xs[pb] + (t * RT) * CIN + c;
                float* op = outp + t * RT * DM;

                float acc[RT];
                #pragma unroll
                for (int nl = 0; nl < RT; ++nl) acc[nl] = bias;

                #pragma unroll
                for (int i = 0; i < RT + 17; ++i) {
                    const float xv = xcol[i * CIN];   // LDS, immediate offset
                    #pragma unroll
                    for (int j = 0; j < 18; ++j) {
                        const int nl = i + j - 17;    // output row fed by (i,j)
                        if (nl >= 0 && nl < RT)
                            acc[nl] = fmaf(w[j], xv, acc[nl]);
                    }
                }

                #pragma unroll
                for (int nl = 0; nl < RT; ++nl)
                    op[nl * DM] = acc[nl];
            }
        } else {
            // Generic path: explicit wrap + validity per conv tap.
            // Only the first and last strip of each batch row (64 / 2048).
            for (int nl = 0; nl < SL; ++nl) {
                const int n = s0 + nl;
                float acc = bias;
                #pragma unroll
                for (int tt = 0; tt < 3; ++tt) {
                    int p = n - 1 + tt;
                    if (p < 0)      p += LSEQ;   // circular pad left
                    if (p >= LSEQ)  p -= LSEQ;   // circular pad right
                    if (p >= 15) {               // delay-embedding validity
                        #pragma unroll
                        for (int m = 0; m < 6; ++m)
                            acc = fmaf(w[3 * m + 2 - tt],
                                       xb[(p - 3 * m) * CIN + c], acc);
                    }
                }
                outp[nl * DM] = acc;
            }
        }
    }
}

extern "C" void kernel_launch(void* const* d_in, const int* in_sizes, int n_in,
                              void* d_out, int out_size)
{
    const float* x      = (const float*)d_in[0];
    const float* conv_w = (const float*)d_in[1];
    const float* conv_b = (const float*)d_in[2];
    const float* left_w = (const float*)d_in[3];
    const float* left_b = (const float*)d_in[4];
    float* out = (float*)d_out;

    tokemb_kernel<<<NBLOCKS, 512>>>(x, conv_w, conv_b, left_w, left_b, out);
}

// round 8
// speedup vs baseline: 1.4724x; 1.4724x over previous
#include <cuda_runtime.h>

// Problem constants (fixed by reference_code)
#define LSEQ 8192
#define BATCH 32
#define CIN 7
#define KER 73            // 512 // 7
#define DM 512
#define RT 16             // output rows per tile
#define SL 256            // rows per block strip (proven R2 shape)
#define TILES (SL / RT)   // 16
#define WROWS (SL + RT + 1)    // 273 window rows: strip + 16 back + 1 fwd
#define WSRC (WROWS * CIN)     // 1911 staged elements
#define XPITCH 276             // row pitch: >=273, 16B-aligned (276*4 % 16 == 0)

// out[b, n, c*73+k] = conv_b[k] + sum_{j=0..17} W2[k][j] * x[b, n+1-j, c]
//   W2[k][j] = conv_w[k][ (j/3)*3 + (2 - j%3) ]
// Conv position p = n-1+t contributes only if (after circular wrap) p >= 15.
// Interior rows 16..L-2 are unconditionally valid (fast path).

__global__ __launch_bounds__(512, 2)
void tokemb_kernel(const float* __restrict__ x,
                   const float* __restrict__ conv_w,
                   const float* __restrict__ conv_b,
                   const float* __restrict__ left_w,
                   const float* __restrict__ left_b,
                   float* __restrict__ out)
{
    const int d  = threadIdx.x;          // output channel 0..511
    const int s0 = blockIdx.x * SL;      // strip start row
    const int b  = blockIdx.y;

    // Per-thread channel / weights / bias (loaded ONCE per block)
    const bool main_ch = (d < CIN * KER);            // d < 511
    const int  c    = main_ch ? (d / KER) : (CIN - 1);
    const float* wsrc = main_ch ? (conv_w + (d % KER) * 18) : left_w;
    const float bias  = main_ch ? conv_b[d % KER] : left_b[0];

    float w[18];
    #pragma unroll
    for (int j = 0; j < 18; ++j)
        w[j] = wsrc[(j / 3) * 3 + 2 - (j % 3)];

    const float* xb = x + (size_t)b * LSEQ * CIN;

    // Stage x[b, s0-16 .. s0+SL, :] TRANSPOSED: xs[c][row], row-contiguous so
    // tile reads vectorize to LDS.128. Index-clamped; clamped junk rows are
    // only consumed by slow-path tiles, which bypass smem entirely.
    __shared__ float xs[CIN][XPITCH];
    {
        const int gbase = (s0 - RT) * CIN;   // may be negative at strip 0
        for (int idx = d; idx < WSRC; idx += 512) {
            int g = gbase + idx;
            g = min(max(g, 0), LSEQ * CIN - 1);
            const int row = idx / CIN;
            const int cc  = idx - row * CIN;
            xs[cc][row] = xb[g];
        }
    }
    __syncthreads();

    float* outp = out + ((size_t)(b * LSEQ + s0)) * DM + d;

    #pragma unroll 1
    for (int t = 0; t < TILES; ++t) {
        const int n0 = s0 + t * RT;
        float* op = outp + t * RT * DM;

        if ((n0 >= 16) && (n0 + RT <= LSEQ - 1)) {
            // xs[c] row l = global row s0-16+l; tile t reads rows t*16..t*16+32
            const float*  xcol = &xs[c][t * RT];
            const float4* xq   = reinterpret_cast<const float4*>(xcol); // 16B-aligned

            float acc[RT];

            // Value-outer fanout with vector loads. For each window value i
            // the tap j feeds output row nl = i + j - 17. Ascending i means
            // the j==17 tap is the FIRST writer of acc[nl] -> fold bias init
            // into it (no separate MOV init).
            #pragma unroll
            for (int g4 = 0; g4 < 8; ++g4) {
                const float4 q = xq[g4];             // LDS.128: window i=4g..4g+3
                const float qv[4] = {q.x, q.y, q.z, q.w};
                #pragma unroll
                for (int c4 = 0; c4 < 4; ++c4) {
                    const int   i  = 4 * g4 + c4;
                    const float xv = qv[c4];
                    #pragma unroll
                    for (int j = 0; j < 18; ++j) {
                        const int nl = i + j - 17;
                        if (nl >= 0 && nl < RT) {
                            if (j == 17) acc[nl] = fmaf(w[17], xv, bias);
                            else         acc[nl] = fmaf(w[j],  xv, acc[nl]);
                        }
                    }
                }
            }
            {   // window value i = 32: only tap j=0 (nl = 15) remains
                const float xv = xcol[32];
                acc[RT - 1] = fmaf(w[0], xv, acc[RT - 1]);
            }

            #pragma unroll
            for (int nl = 0; nl < RT; ++nl)
                op[nl * DM] = acc[nl];
        } else {
            // Generic path: explicit wrap + validity per conv tap. Only the
            // first and last tile of each sequence land here.
            for (int nl = 0; nl < RT; ++nl) {
                const int n = n0 + nl;
                float acc = bias;
                #pragma unroll
                for (int tt = 0; tt < 3; ++tt) {
                    int p = n - 1 + tt;
                    if (p < 0)      p += LSEQ;   // circular pad left
                    if (p >= LSEQ)  p -= LSEQ;   // circular pad right
                    if (p >= 15) {               // delay-embedding validity
                        #pragma unroll
                        for (int m = 0; m < 6; ++m)
                            acc = fmaf(w[3 * m + 2 - tt],
                                       xb[(p - 3 * m) * CIN + c], acc);
                    }
                }
                op[nl * DM] = acc;
            }
        }
    }
}

extern "C" void kernel_launch(void* const* d_in, const int* in_sizes, int n_in,
                              void* d_out, int out_size)
{
    const float* x      = (const float*)d_in[0];
    const float* conv_w = (const float*)d_in[1];
    const float* conv_b = (const float*)d_in[2];
    const float* left_w = (const float*)d_in[3];
    const float* left_b = (const float*)d_in[4];
    float* out = (float*)d_out;

    dim3 grid(LSEQ / SL, BATCH);   // (32, 32) = 1024 blocks
    tokemb_kernel<<<grid, 512>>>(x, conv_w, conv_b, left_w, left_b, out);
}